// round 2
// baseline (speedup 1.0000x reference)
#include <cuda_runtime.h>
#include <cstdint>

// Problem constants
#define NROWS 32768        // B*T = 64*512
#define DDIM  256
#define KCODES 1024
#define QLAYERS 8
#define BTD   (NROWS*DDIM)         // 8388608
#define IDX_BASE (BTD + 1)         // output layout: [output | loss | indices]

// GEMM tiling
#define BM 128
#define BN 128
#define BD 16
#define SSTRIDE 132                // padded smem stride (16B-aligned, conflict-light)
#define NBLK (NROWS / BM)          // 256 blocks per layer

// Scratch (static device memory — no allocation in kernel_launch)
__device__ float  g_resid[NROWS * DDIM];     // running residual, 33.5 MB
__device__ float  g_C[NROWS];                // per-row ||residual||^2 (fp32, from fp64)
__device__ float  g_b[QLAYERS * KCODES];     // per-code ||e||^2
__device__ double g_losspart[QLAYERS * NBLK];// deterministic loss partials

#define INFF __int_as_float(0x7f800000)

// ---------------------------------------------------------------------------
// Prep 1: codebook squared norms  b[q*K + k] = sum_d e[q,k,d]^2
// ---------------------------------------------------------------------------
__global__ void prep_b_kernel(const float* __restrict__ emb)
{
    int warp = (blockIdx.x * blockDim.x + threadIdx.x) >> 5;
    int lane = threadIdx.x & 31;
    if (warp < QLAYERS * KCODES) {
        const float* e = emb + (size_t)warp * DDIM;
        float s = 0.f;
        #pragma unroll
        for (int d = lane; d < DDIM; d += 32) {
            float v = e[d];
            s = __fmaf_rn(v, v, s);
        }
        #pragma unroll
        for (int o = 16; o; o >>= 1) s += __shfl_xor_sync(0xffffffffu, s, o);
        if (lane == 0) g_b[warp] = s;
    }
}

// ---------------------------------------------------------------------------
// Prep 2: copy x -> residual, compute row norms C (fp64 accumulate -> fp32)
// ---------------------------------------------------------------------------
__global__ void prep_rows_kernel(const float* __restrict__ x)
{
    int warp  = (blockIdx.x * blockDim.x + threadIdx.x) >> 5;
    int lane  = threadIdx.x & 31;
    int nwarp = (gridDim.x * blockDim.x) >> 5;
    for (int row = warp; row < NROWS; row += nwarp) {
        const float4* xr = reinterpret_cast<const float4*>(x + (size_t)row * DDIM);
        float4*       rr = reinterpret_cast<float4*>(g_resid + (size_t)row * DDIM);
        double s = 0.0;
        #pragma unroll
        for (int d4 = lane; d4 < DDIM / 4; d4 += 32) {
            float4 v = xr[d4];
            rr[d4] = v;
            s += (double)v.x * v.x + (double)v.y * v.y
               + (double)v.z * v.z + (double)v.w * v.w;
        }
        #pragma unroll
        for (int o = 16; o; o >>= 1) s += __shfl_xor_sync(0xffffffffu, s, o);
        if (lane == 0) g_C[row] = (float)s;
    }
}

// ---------------------------------------------------------------------------
// Per-layer fused kernel:
//   - 128 rows x 1024 codes distance GEMM (fp32, 8x8 register tiles)
//   - reference-rounding dist = fl(fl(C+b) - 2*m), first-index argmin
//   - epilogue: residual -= e[idx] in place, new C (fp64), idx out, loss partial
// ---------------------------------------------------------------------------
__global__ __launch_bounds__(256, 2)
void vq_layer_kernel(const float* __restrict__ emb_all, int q,
                     float* __restrict__ d_out)
{
    __shared__ float As[BD][SSTRIDE];
    __shared__ float Bs[BD][SSTRIDE];
    __shared__ int   idx_s[BM];
    __shared__ double warp_loss[8];

    const float* emb = emb_all + (size_t)q * KCODES * DDIM;

    const int tid = threadIdx.x;
    const int tx  = tid & 15;     // 0..15 (col group)
    const int ty  = tid >> 4;     // 0..15 (row group)
    const int rowbase = blockIdx.x * BM;

    // This thread's 8 local rows: ty*4+i (i<4), 64+ty*4+(i-4)
    float Cr[8];
    #pragma unroll
    for (int i = 0; i < 8; i++) {
        int rl = (i < 4) ? (ty * 4 + i) : (64 + ty * 4 + (i - 4));
        Cr[i] = g_C[rowbase + rl];
    }

    float bestv[8];
    int   besti[8];
    #pragma unroll
    for (int i = 0; i < 8; i++) { bestv[i] = INFF; besti[i] = 0x7fffffff; }

    // Loader indices: each thread loads 2 A-rows and 2 B-rows (as float4) per d-chunk
    const int lr = tid >> 2;   // 0..63
    const int ld4 = tid & 3;   // 0..3  -> d offset ld4*4

    for (int cb = 0; cb < KCODES; cb += BN) {
        float acc[8][8];
        #pragma unroll
        for (int i = 0; i < 8; i++)
            #pragma unroll
            for (int j = 0; j < 8; j++) acc[i][j] = 0.f;

        for (int db = 0; db < DDIM; db += BD) {
            float4 a0 = *reinterpret_cast<const float4*>(
                g_resid + (size_t)(rowbase + lr) * DDIM + db + ld4 * 4);
            float4 a1 = *reinterpret_cast<const float4*>(
                g_resid + (size_t)(rowbase + lr + 64) * DDIM + db + ld4 * 4);
            float4 b0 = *reinterpret_cast<const float4*>(
                emb + (size_t)(cb + lr) * DDIM + db + ld4 * 4);
            float4 b1 = *reinterpret_cast<const float4*>(
                emb + (size_t)(cb + lr + 64) * DDIM + db + ld4 * 4);

            __syncthreads();   // previous iter's smem reads done
            As[ld4 * 4 + 0][lr] = a0.x;  As[ld4 * 4 + 1][lr] = a0.y;
            As[ld4 * 4 + 2][lr] = a0.z;  As[ld4 * 4 + 3][lr] = a0.w;
            As[ld4 * 4 + 0][lr + 64] = a1.x;  As[ld4 * 4 + 1][lr + 64] = a1.y;
            As[ld4 * 4 + 2][lr + 64] = a1.z;  As[ld4 * 4 + 3][lr + 64] = a1.w;
            Bs[ld4 * 4 + 0][lr] = b0.x;  Bs[ld4 * 4 + 1][lr] = b0.y;
            Bs[ld4 * 4 + 2][lr] = b0.z;  Bs[ld4 * 4 + 3][lr] = b0.w;
            Bs[ld4 * 4 + 0][lr + 64] = b1.x;  Bs[ld4 * 4 + 1][lr + 64] = b1.y;
            Bs[ld4 * 4 + 2][lr + 64] = b1.z;  Bs[ld4 * 4 + 3][lr + 64] = b1.w;
            __syncthreads();

            #pragma unroll
            for (int dd = 0; dd < BD; dd++) {
                float4 af0 = *reinterpret_cast<const float4*>(&As[dd][ty * 4]);
                float4 af1 = *reinterpret_cast<const float4*>(&As[dd][64 + ty * 4]);
                float4 bf0 = *reinterpret_cast<const float4*>(&Bs[dd][tx * 4]);
                float4 bf1 = *reinterpret_cast<const float4*>(&Bs[dd][64 + tx * 4]);
                float a[8] = {af0.x, af0.y, af0.z, af0.w, af1.x, af1.y, af1.z, af1.w};
                float b[8] = {bf0.x, bf0.y, bf0.z, bf0.w, bf1.x, bf1.y, bf1.z, bf1.w};
                #pragma unroll
                for (int i = 0; i < 8; i++)
                    #pragma unroll
                    for (int j = 0; j < 8; j++)
                        acc[i][j] = __fmaf_rn(a[i], b[j], acc[i][j]);
            }
        }

        // per-chunk argmin with reference rounding + first-index ties
        float bcol[8];
        int   ccol[8];
        #pragma unroll
        for (int j = 0; j < 8; j++) {
            int c = cb + ((j < 4) ? (tx * 4 + j) : (64 + tx * 4 + (j - 4)));
            ccol[j] = c;
            bcol[j] = g_b[q * KCODES + c];
        }
        #pragma unroll
        for (int i = 0; i < 8; i++) {
            float bv = INFF;
            int   bi = 0x7fffffff;
            #pragma unroll
            for (int j = 0; j < 8; j++) {
                float t    = __fadd_rn(Cr[i], bcol[j]);
                float dist = __fmaf_rn(-2.0f, acc[i][j], t); // == fl(t - 2m), 2m exact
                if (dist < bv || (dist == bv && ccol[j] < bi)) { bv = dist; bi = ccol[j]; }
            }
            #pragma unroll
            for (int o = 8; o; o >>= 1) {
                float ov = __shfl_xor_sync(0xffffffffu, bv, o);
                int   oi = __shfl_xor_sync(0xffffffffu, bi, o);
                if (ov < bv || (ov == bv && oi < bi)) { bv = ov; bi = oi; }
            }
            if (bv < bestv[i] || (bv == bestv[i] && bi < besti[i])) {
                bestv[i] = bv; besti[i] = bi;
            }
        }
    }

    if (tx == 0) {
        #pragma unroll
        for (int i = 0; i < 8; i++) {
            int rl = (i < 4) ? (ty * 4 + i) : (64 + ty * 4 + (i - 4));
            idx_s[rl] = besti[i];
        }
    }
    __syncthreads();

    // Epilogue: residual update, new C, loss partial, index output
    const int w    = tid >> 5;
    const int lane = tid & 31;
    double lsum = 0.0;
    for (int rr = w * 16; rr < w * 16 + 16; rr++) {
        int idx = idx_s[rr];
        const float* ev = emb + (size_t)idx * DDIM;
        float* rp = g_resid + (size_t)(rowbase + rr) * DDIM;
        double s = 0.0;
        #pragma unroll
        for (int d = lane; d < DDIM; d += 32) {
            float rn = __fsub_rn(rp[d], ev[d]);   // elementwise, matches reference op
            rp[d] = rn;
            s += (double)rn * rn;
        }
        #pragma unroll
        for (int o = 16; o; o >>= 1) s += __shfl_xor_sync(0xffffffffu, s, o);
        if (lane == 0) {
            g_C[rowbase + rr] = (float)s;
            lsum += s;
            d_out[IDX_BASE + (size_t)q * NROWS + rowbase + rr] = (float)idx;
        }
    }
    if (lane == 0) warp_loss[w] = lsum;
    __syncthreads();
    if (tid == 0) {
        double t = 0.0;
        #pragma unroll
        for (int i = 0; i < 8; i++) t += warp_loss[i];
        g_losspart[q * NBLK + blockIdx.x] = t;
    }
}

// ---------------------------------------------------------------------------
// Final: output = x - residual ; total_loss = 1.25 * sum(partials) / (N*D)
// ---------------------------------------------------------------------------
__global__ void final_kernel(const float* __restrict__ x, float* __restrict__ d_out)
{
    size_t i = (size_t)blockIdx.x * blockDim.x + threadIdx.x;
    if (i < (size_t)BTD / 4) {
        const float4 xv = reinterpret_cast<const float4*>(x)[i];
        const float4 rv = reinterpret_cast<const float4*>(g_resid)[i];
        float4 o;
        o.x = xv.x - rv.x; o.y = xv.y - rv.y;
        o.z = xv.z - rv.z; o.w = xv.w - rv.w;
        reinterpret_cast<float4*>(d_out)[i] = o;
    }

    // Block 0: parallel deterministic loss reduction (2048 fp64 partials)
    if (blockIdx.x == 0) {
        __shared__ double red[256];
        int t = threadIdx.x;
        double s = 0.0;
        // fixed traversal order per thread -> deterministic fp64 sum tree
        for (int k = t; k < QLAYERS * NBLK; k += 256) s += g_losspart[k];
        red[t] = s;
        __syncthreads();
        for (int o = 128; o; o >>= 1) {
            if (t < o) red[t] += red[t + o];
            __syncthreads();
        }
        if (t == 0) d_out[BTD] = (float)(1.25 * red[0] / (double)BTD);
    }
}

// ---------------------------------------------------------------------------
// Entry point
// ---------------------------------------------------------------------------
extern "C" void kernel_launch(void* const* d_in, const int* in_sizes, int n_in,
                              void* d_out, int out_size)
{
    const float* x   = (const float*)d_in[0];   // [64,512,256] f32
    const float* emb = (const float*)d_in[1];   // [8,1024,256] f32
    float* out = (float*)d_out;

    // codebook norms: 8192 warps = 1024 blocks of 256 threads
    prep_b_kernel<<<(QLAYERS * KCODES * 32 + 255) / 256, 256>>>(emb);
    // residual init + row norms: 2048 warps, 16 rows per warp
    prep_rows_kernel<<<256, 256>>>(x);

    for (int q = 0; q < QLAYERS; q++) {
        vq_layer_kernel<<<NBLK, 256>>>(emb, q, out);
    }

    final_kernel<<<(BTD / 4 + 255) / 256, 256>>>(x, out);
    (void)in_sizes; (void)n_in; (void)out_size;
}

// round 3
// speedup vs baseline: 1.0735x; 1.0735x over previous
#include <cuda_runtime.h>
#include <cstdint>

// Problem constants
#define NROWS 32768        // B*T = 64*512
#define DDIM  256
#define KCODES 1024
#define QLAYERS 8
#define BTD   (NROWS*DDIM)         // 8388608
#define IDX_BASE (BTD + 1)         // output layout: [output | loss | indices]

// GEMM tiling
#define BM 128
#define BN 128
#define BD 16
#define SSTRIDE 132                // padded smem stride (16B-aligned, conflict-light)
#define NBLK (NROWS / BM)          // 256 blocks per layer

// Scratch (static device memory — no allocation in kernel_launch)
__device__ float  g_resid[NROWS * DDIM];     // running residual, 33.5 MB
__device__ float  g_C[NROWS];                // per-row ||residual||^2 (fp32, from fp64)
__device__ float  g_b[QLAYERS * KCODES];     // per-code ||e||^2
__device__ double g_losspart[QLAYERS * NBLK];// deterministic loss partials

#define INFF __int_as_float(0x7f800000)

// Packed fp32x2 FMA (Blackwell): two IEEE fp32 FMAs per instruction,
// per-lane rounding identical to scalar __fmaf_rn.
#define FFMA2(d, a, b, c) \
    asm("fma.rn.f32x2 %0, %1, %2, %3;" : "=l"(d) : "l"(a), "l"(b), "l"(c))
#define PACK_DUP(d, s) \
    asm("mov.b64 %0, {%1, %1};" : "=l"(d) : "r"(__float_as_uint(s)))
#define UNPACK2(lo, hi, s) \
    asm("mov.b64 {%0, %1}, %2;" : "=f"(lo), "=f"(hi) : "l"(s))

// ---------------------------------------------------------------------------
// Prep 1: codebook squared norms  b[q*K + k] = sum_d e[q,k,d]^2
// ---------------------------------------------------------------------------
__global__ void prep_b_kernel(const float* __restrict__ emb)
{
    int warp = (blockIdx.x * blockDim.x + threadIdx.x) >> 5;
    int lane = threadIdx.x & 31;
    if (warp < QLAYERS * KCODES) {
        const float* e = emb + (size_t)warp * DDIM;
        float s = 0.f;
        #pragma unroll
        for (int d = lane; d < DDIM; d += 32) {
            float v = e[d];
            s = __fmaf_rn(v, v, s);
        }
        #pragma unroll
        for (int o = 16; o; o >>= 1) s += __shfl_xor_sync(0xffffffffu, s, o);
        if (lane == 0) g_b[warp] = s;
    }
}

// ---------------------------------------------------------------------------
// Prep 2: copy x -> residual, compute row norms C (fp64 accumulate -> fp32)
// ---------------------------------------------------------------------------
__global__ void prep_rows_kernel(const float* __restrict__ x)
{
    int warp  = (blockIdx.x * blockDim.x + threadIdx.x) >> 5;
    int lane  = threadIdx.x & 31;
    int nwarp = (gridDim.x * blockDim.x) >> 5;
    for (int row = warp; row < NROWS; row += nwarp) {
        const float4* xr = reinterpret_cast<const float4*>(x + (size_t)row * DDIM);
        float4*       rr = reinterpret_cast<float4*>(g_resid + (size_t)row * DDIM);
        double s = 0.0;
        #pragma unroll
        for (int d4 = lane; d4 < DDIM / 4; d4 += 32) {
            float4 v = xr[d4];
            rr[d4] = v;
            s += (double)v.x * v.x + (double)v.y * v.y
               + (double)v.z * v.z + (double)v.w * v.w;
        }
        #pragma unroll
        for (int o = 16; o; o >>= 1) s += __shfl_xor_sync(0xffffffffu, s, o);
        if (lane == 0) g_C[row] = (float)s;
    }
}

// ---------------------------------------------------------------------------
// Per-layer fused kernel:
//   - 128 rows x 1024 codes distance GEMM, fp32 via packed fma.rn.f32x2
//   - reference-rounding dist = fl(fl(C+b) - 2*m), first-index argmin
//   - epilogue: residual -= e[idx] in place, new C (fp64), idx out, loss partial
// ---------------------------------------------------------------------------
__global__ __launch_bounds__(256, 2)
void vq_layer_kernel(const float* __restrict__ emb_all, int q,
                     float* __restrict__ d_out)
{
    __shared__ float As[BD][SSTRIDE];
    __shared__ float Bs[BD][SSTRIDE];
    __shared__ int   idx_s[BM];
    __shared__ double warp_loss[8];

    const float* emb = emb_all + (size_t)q * KCODES * DDIM;

    const int tid = threadIdx.x;
    const int tx  = tid & 15;     // 0..15 (col group)
    const int ty  = tid >> 4;     // 0..15 (row group)
    const int rowbase = blockIdx.x * BM;

    // This thread's 8 local rows: ty*4+i (i<4), 64+ty*4+(i-4)
    float Cr[8];
    #pragma unroll
    for (int i = 0; i < 8; i++) {
        int rl = (i < 4) ? (ty * 4 + i) : (64 + ty * 4 + (i - 4));
        Cr[i] = g_C[rowbase + rl];
    }

    float bestv[8];
    int   besti[8];
    #pragma unroll
    for (int i = 0; i < 8; i++) { bestv[i] = INFF; besti[i] = 0x7fffffff; }

    // Loader indices: each thread loads 2 A-rows and 2 B-rows (as float4) per d-chunk
    const int lr = tid >> 2;   // 0..63
    const int ld4 = tid & 3;   // 0..3  -> d offset ld4*4

    for (int cb = 0; cb < KCODES; cb += BN) {
        // 8 rows x 4 packed column-pairs of f32x2 accumulators (= 8x8 scalar)
        unsigned long long acc2[8][4];
        #pragma unroll
        for (int i = 0; i < 8; i++)
            #pragma unroll
            for (int jj = 0; jj < 4; jj++) acc2[i][jj] = 0ull;

        for (int db = 0; db < DDIM; db += BD) {
            float4 a0 = *reinterpret_cast<const float4*>(
                g_resid + (size_t)(rowbase + lr) * DDIM + db + ld4 * 4);
            float4 a1 = *reinterpret_cast<const float4*>(
                g_resid + (size_t)(rowbase + lr + 64) * DDIM + db + ld4 * 4);
            float4 b0 = *reinterpret_cast<const float4*>(
                emb + (size_t)(cb + lr) * DDIM + db + ld4 * 4);
            float4 b1 = *reinterpret_cast<const float4*>(
                emb + (size_t)(cb + lr + 64) * DDIM + db + ld4 * 4);

            __syncthreads();   // previous iter's smem reads done
            As[ld4 * 4 + 0][lr] = a0.x;  As[ld4 * 4 + 1][lr] = a0.y;
            As[ld4 * 4 + 2][lr] = a0.z;  As[ld4 * 4 + 3][lr] = a0.w;
            As[ld4 * 4 + 0][lr + 64] = a1.x;  As[ld4 * 4 + 1][lr + 64] = a1.y;
            As[ld4 * 4 + 2][lr + 64] = a1.z;  As[ld4 * 4 + 3][lr + 64] = a1.w;
            Bs[ld4 * 4 + 0][lr] = b0.x;  Bs[ld4 * 4 + 1][lr] = b0.y;
            Bs[ld4 * 4 + 2][lr] = b0.z;  Bs[ld4 * 4 + 3][lr] = b0.w;
            Bs[ld4 * 4 + 0][lr + 64] = b1.x;  Bs[ld4 * 4 + 1][lr + 64] = b1.y;
            Bs[ld4 * 4 + 2][lr + 64] = b1.z;  Bs[ld4 * 4 + 3][lr + 64] = b1.w;
            __syncthreads();

            #pragma unroll
            for (int dd = 0; dd < BD; dd++) {
                float4 af0 = *reinterpret_cast<const float4*>(&As[dd][ty * 4]);
                float4 af1 = *reinterpret_cast<const float4*>(&As[dd][64 + ty * 4]);
                // B column pairs are packed for free: (c0,c1),(c2,c3) within each float4
                ulonglong2 bp0 = *reinterpret_cast<const ulonglong2*>(&Bs[dd][tx * 4]);
                ulonglong2 bp1 = *reinterpret_cast<const ulonglong2*>(&Bs[dd][64 + tx * 4]);
                unsigned long long b2[4] = {bp0.x, bp0.y, bp1.x, bp1.y};
                float a[8] = {af0.x, af0.y, af0.z, af0.w, af1.x, af1.y, af1.z, af1.w};
                #pragma unroll
                for (int i = 0; i < 8; i++) {
                    unsigned long long a2;
                    PACK_DUP(a2, a[i]);
                    #pragma unroll
                    for (int jj = 0; jj < 4; jj++)
                        FFMA2(acc2[i][jj], a2, b2[jj], acc2[i][jj]);
                }
            }
        }

        // per-chunk argmin with reference rounding + first-index ties
        float bcol[8];
        int   ccol[8];
        #pragma unroll
        for (int j = 0; j < 8; j++) {
            int c = cb + ((j < 4) ? (tx * 4 + j) : (64 + tx * 4 + (j - 4)));
            ccol[j] = c;
            bcol[j] = g_b[q * KCODES + c];
        }
        #pragma unroll
        for (int i = 0; i < 8; i++) {
            float bv = INFF;
            int   bi = 0x7fffffff;
            #pragma unroll
            for (int jj = 0; jj < 4; jj++) {
                float m0, m1;
                UNPACK2(m0, m1, acc2[i][jj]);
                float t0    = __fadd_rn(Cr[i], bcol[jj * 2 + 0]);
                float d0    = __fmaf_rn(-2.0f, m0, t0); // == fl(t - 2m), 2m exact
                if (d0 < bv || (d0 == bv && ccol[jj * 2 + 0] < bi)) { bv = d0; bi = ccol[jj * 2 + 0]; }
                float t1    = __fadd_rn(Cr[i], bcol[jj * 2 + 1]);
                float d1    = __fmaf_rn(-2.0f, m1, t1);
                if (d1 < bv || (d1 == bv && ccol[jj * 2 + 1] < bi)) { bv = d1; bi = ccol[jj * 2 + 1]; }
            }
            #pragma unroll
            for (int o = 8; o; o >>= 1) {
                float ov = __shfl_xor_sync(0xffffffffu, bv, o);
                int   oi = __shfl_xor_sync(0xffffffffu, bi, o);
                if (ov < bv || (ov == bv && oi < bi)) { bv = ov; bi = oi; }
            }
            if (bv < bestv[i] || (bv == bestv[i] && bi < besti[i])) {
                bestv[i] = bv; besti[i] = bi;
            }
        }
    }

    if (tx == 0) {
        #pragma unroll
        for (int i = 0; i < 8; i++) {
            int rl = (i < 4) ? (ty * 4 + i) : (64 + ty * 4 + (i - 4));
            idx_s[rl] = besti[i];
        }
    }
    __syncthreads();

    // Epilogue: residual update, new C, loss partial, index output
    const int w    = tid >> 5;
    const int lane = tid & 31;
    double lsum = 0.0;
    for (int rr = w * 16; rr < w * 16 + 16; rr++) {
        int idx = idx_s[rr];
        const float* ev = emb + (size_t)idx * DDIM;
        float* rp = g_resid + (size_t)(rowbase + rr) * DDIM;
        double s = 0.0;
        #pragma unroll
        for (int d = lane; d < DDIM; d += 32) {
            float rn = __fsub_rn(rp[d], ev[d]);   // elementwise, matches reference op
            rp[d] = rn;
            s += (double)rn * rn;
        }
        #pragma unroll
        for (int o = 16; o; o >>= 1) s += __shfl_xor_sync(0xffffffffu, s, o);
        if (lane == 0) {
            g_C[rowbase + rr] = (float)s;
            lsum += s;
            d_out[IDX_BASE + (size_t)q * NROWS + rowbase + rr] = (float)idx;
        }
    }
    if (lane == 0) warp_loss[w] = lsum;
    __syncthreads();
    if (tid == 0) {
        double t = 0.0;
        #pragma unroll
        for (int i = 0; i < 8; i++) t += warp_loss[i];
        g_losspart[q * NBLK + blockIdx.x] = t;
    }
}

// ---------------------------------------------------------------------------
// Final: output = x - residual ; total_loss = 1.25 * sum(partials) / (N*D)
// ---------------------------------------------------------------------------
__global__ void final_kernel(const float* __restrict__ x, float* __restrict__ d_out)
{
    size_t i = (size_t)blockIdx.x * blockDim.x + threadIdx.x;
    if (i < (size_t)BTD / 4) {
        const float4 xv = reinterpret_cast<const float4*>(x)[i];
        const float4 rv = reinterpret_cast<const float4*>(g_resid)[i];
        float4 o;
        o.x = xv.x - rv.x; o.y = xv.y - rv.y;
        o.z = xv.z - rv.z; o.w = xv.w - rv.w;
        reinterpret_cast<float4*>(d_out)[i] = o;
    }

    // Block 0: parallel deterministic loss reduction (2048 fp64 partials)
    if (blockIdx.x == 0) {
        __shared__ double red[256];
        int t = threadIdx.x;
        double s = 0.0;
        for (int k = t; k < QLAYERS * NBLK; k += 256) s += g_losspart[k];
        red[t] = s;
        __syncthreads();
        for (int o = 128; o; o >>= 1) {
            if (t < o) red[t] += red[t + o];
            __syncthreads();
        }
        if (t == 0) d_out[BTD] = (float)(1.25 * red[0] / (double)BTD);
    }
}

// ---------------------------------------------------------------------------
// Entry point
// ---------------------------------------------------------------------------
extern "C" void kernel_launch(void* const* d_in, const int* in_sizes, int n_in,
                              void* d_out, int out_size)
{
    const float* x   = (const float*)d_in[0];   // [64,512,256] f32
    const float* emb = (const float*)d_in[1];   // [8,1024,256] f32
    float* out = (float*)d_out;

    prep_b_kernel<<<(QLAYERS * KCODES * 32 + 255) / 256, 256>>>(emb);
    prep_rows_kernel<<<256, 256>>>(x);

    for (int q = 0; q < QLAYERS; q++) {
        vq_layer_kernel<<<NBLK, 256>>>(emb, q, out);
    }

    final_kernel<<<(BTD / 4 + 255) / 256, 256>>>(x, out);
    (void)in_sizes; (void)n_in; (void)out_size;
}